// round 11
// baseline (speedup 1.0000x reference)
#include <cuda_runtime.h>
#include <cuda_fp16.h>
#include <cstdint>

#define N_SAMP 4096
#define V 256
#define VM1 255
#define NH 64
#define NCOLS (V * NH)   // 16384
#define TILES 4096
#define GRID_MAIN 296

__device__ __half g_Ah[N_SAMP * V];   // data as fp16 [4096][256]
__device__ __half g_Bh[NCOLS * V];    // B^T: [gc][j]
__device__ float  g_gate[NCOLS];      // neurons[h,c]*w_out[c,h]

__device__ __forceinline__ uint32_t smem_u32(const void* p) {
    uint32_t a;
    asm("{ .reg .u64 t; cvta.to.shared.u64 t, %1; cvt.u32.u64 %0, t; }" : "=r"(a) : "l"(p));
    return a;
}
#define CP_ASYNC16(dst_u32, src_ptr) \
    asm volatile("cp.async.cg.shared.global [%0], [%1], 16;" :: "r"(dst_u32), "l"(src_ptr) : "memory")
#define CP_COMMIT() asm volatile("cp.async.commit_group;" ::: "memory")

// ---------------------------------------------------------------------------
// Merged prep (unchanged)
// ---------------------------------------------------------------------------
__global__ __launch_bounds__(256) void prep_kernel(
    const float4* __restrict__ data4,
    const float*  __restrict__ adj,
    const float*  __restrict__ neurons,
    const float*  __restrict__ w_in,
    const float*  __restrict__ w_out,
    float4* __restrict__ out_adj4)
{
    __shared__ float s[64][65];
    __shared__ float adjv[64];
    const int tid = threadIdx.x;

    if (blockIdx.x < 1024) {
        int idx = blockIdx.x * 256 + tid;
        if (idx < (N_SAMP * V) / 4) {
            float4 v = data4[idx];
            __half2* dst = (__half2*)(g_Ah + idx * 4);
            dst[0] = __floats2half2_rn(v.x, v.y);
            dst[1] = __floats2half2_rn(v.z, v.w);
        }
        if (idx < (V * V) / 4) out_adj4[idx] = ((const float4*)adj)[idx];
        if (idx < NCOLS / 4) {
            int gc = idx * 4;
            int c = gc >> 6, h = gc & 63;
            float4 g;
            g.x = neurons[(h + 0) * V + c] * w_out[gc + 0];
            g.y = neurons[(h + 1) * V + c] * w_out[gc + 1];
            g.z = neurons[(h + 2) * V + c] * w_out[gc + 2];
            g.w = neurons[(h + 3) * V + c] * w_out[gc + 3];
            *(float4*)(g_gate + gc) = g;
        }
    } else {
        const int bid = blockIdx.x - 1024;
        const int c   = bid >> 2;
        const int jb  = bid & 3;
        const int h   = tid & 63;
        const int kk4 = tid >> 6;

        if (tid < 64) {
            int j = jb * 64 + tid;
            adjv[tid] = (j == c) ? 0.0f : adj[j * V + c];
        }
        #pragma unroll
        for (int jj0 = 0; jj0 < 64; jj0 += 4) {
            int jj = jj0 + kk4;
            int j  = jb * 64 + jj;
            float w = 0.0f;
            if (j != c) {
                int k = j - (j > c ? 1 : 0);
                w = w_in[(c * VM1 + k) * NH + h];
            }
            s[jj][h] = w;
        }
        __syncthreads();
        #pragma unroll
        for (int h0 = 0; h0 < 64; h0 += 4) {
            int hh = h0 + (tid >> 6);
            int jj = tid & 63;
            float w = s[jj][hh] * adjv[jj];
            g_Bh[(c * 64 + hh) * V + jb * 64 + jj] = __float2half_rn(w);
        }
    }
}

// ---------------------------------------------------------------------------
// Persistent fused GEMM: continuous 3-stage cp.async ring across tiles,
// one __syncthreads per stage; epilogue (f16x2 tanh) overlaps next-tile loads.
// CTA 128x128, 4 warps as 2x2, warp tile 64x64, 2 CTAs/SM.
// ---------------------------------------------------------------------------
#define BK 64
#define A_STAGE_BYTES 16384
#define STAGE_BYTES 32768
#define NSTAGE 3
#define SMEM_TOTAL (NSTAGE * STAGE_BYTES) // 96KB

// prefetch global stage kk (tile = bx + (kk>>2)*GRID_MAIN, k0 = (kk&3)*64)
__device__ __forceinline__ void prefetch_k(uint32_t sb, int bx, int kk, int buf3,
                                           int ldr, int ldq) {
    const int tile = bx + (kk >> 2) * GRID_MAIN;
    const int m0   = (tile >> 7) << 7;
    const int gc0  = (tile & 127) << 7;
    const int k0   = (kk & 3) * BK;
    uint32_t sa = sb + (uint32_t)(buf3 * STAGE_BYTES);
    uint32_t sB = sa + A_STAGE_BYTES;
    #pragma unroll
    for (int i = 0; i < 8; i++) {
        int r = ldr + i * 16;
        uint32_t dsw = (uint32_t)(r * 128 + ((ldq ^ (r & 7)) << 4));
        CP_ASYNC16(sa + dsw, g_Ah + (m0 + r) * V + k0 + ldq * 8);
        CP_ASYNC16(sB + dsw, g_Bh + (gc0 + r) * V + k0 + ldq * 8);
    }
    CP_COMMIT();
}

__global__ __launch_bounds__(128, 2)
void fused_mma_kernel(const float* __restrict__ b_in,
                      const float* __restrict__ b_out,
                      float* __restrict__ out) {
    extern __shared__ __align__(16) char smem[];
    const uint32_t sb = smem_u32(smem);

    const int tid  = threadIdx.x;
    const int wid  = tid >> 5;
    const int lane = tid & 31;
    const int wr   = wid & 1;
    const int wc   = wid >> 1;
    const int ldr  = tid >> 3;
    const int ldq  = tid & 7;
    const int g    = lane >> 2;
    const int tig  = lane & 3;

    const int bx = blockIdx.x;
    const int T  = (TILES - bx + GRID_MAIN - 1) / GRID_MAIN;   // tiles for this CTA
    const int last_k = T * 4 - 1;

    // preamble: prefetch stages 0,1 into buffers 0,1
    prefetch_k(sb, bx, 0, 0, ldr, ldq);
    prefetch_k(sb, bx, 1, 1, ldr, ldq);

    int k  = 0;      // global stage counter
    int kb = 0;      // k % 3
    int pb = 2;      // (k+2) % 3

    for (int i = 0; i < T; i++) {
        const int tile = bx + i * GRID_MAIN;
        const int m0   = (tile >> 7) << 7;
        const int gc0  = (tile & 127) << 7;

        float d[4][8][4];
        #pragma unroll
        for (int mt = 0; mt < 4; mt++)
            #pragma unroll
            for (int nt = 0; nt < 8; nt++)
                #pragma unroll
                for (int v = 0; v < 4; v++) d[mt][nt][v] = 0.0f;

        #pragma unroll
        for (int t = 0; t < 4; t++) {
            if (k < last_k) asm volatile("cp.async.wait_group 1;" ::: "memory");
            else            asm volatile("cp.async.wait_group 0;" ::: "memory");
            __syncthreads();

            if (k + 2 <= last_k)
                prefetch_k(sb, bx, k + 2, pb, ldr, ldq);

            const uint32_t sa = sb + (uint32_t)(kb * STAGE_BYTES);
            const uint32_t sB = sa + A_STAGE_BYTES;

            #pragma unroll
            for (int ks = 0; ks < 4; ks++) {
                uint32_t a[4][4];
                #pragma unroll
                for (int mt = 0; mt < 4; mt++) {
                    int r = wr * 64 + mt * 16 + (lane & 15);
                    int q = ks * 2 + (lane >> 4);
                    uint32_t addr = sa + r * 128 + ((q ^ (r & 7)) << 4);
                    asm volatile("ldmatrix.sync.aligned.m8n8.x4.shared.b16 {%0,%1,%2,%3}, [%4];"
                        : "=r"(a[mt][0]), "=r"(a[mt][1]), "=r"(a[mt][2]), "=r"(a[mt][3])
                        : "r"(addr));
                }
                uint32_t bf[8][2];
                #pragma unroll
                for (int p = 0; p < 4; p++) {
                    int r = wc * 64 + p * 16 + (lane & 7) + ((lane >> 4) << 3);
                    int q = ks * 2 + ((lane >> 3) & 1);
                    uint32_t addr = sB + r * 128 + ((q ^ (r & 7)) << 4);
                    uint32_t r0, r1, r2, r3;
                    asm volatile("ldmatrix.sync.aligned.m8n8.x4.shared.b16 {%0,%1,%2,%3}, [%4];"
                        : "=r"(r0), "=r"(r1), "=r"(r2), "=r"(r3) : "r"(addr));
                    bf[p * 2][0] = r0; bf[p * 2][1] = r1;
                    bf[p * 2 + 1][0] = r2; bf[p * 2 + 1][1] = r3;
                }
                #pragma unroll
                for (int mt = 0; mt < 4; mt++)
                    #pragma unroll
                    for (int nt = 0; nt < 8; nt++) {
                        asm volatile(
                            "mma.sync.aligned.m16n8k16.row.col.f32.f16.f16.f32 "
                            "{%0,%1,%2,%3}, {%4,%5,%6,%7}, {%8,%9}, {%0,%1,%2,%3};"
                            : "+f"(d[mt][nt][0]), "+f"(d[mt][nt][1]),
                              "+f"(d[mt][nt][2]), "+f"(d[mt][nt][3])
                            : "r"(a[mt][0]), "r"(a[mt][1]), "r"(a[mt][2]), "r"(a[mt][3]),
                              "r"(bf[nt][0]), "r"(bf[nt][1]));
                    }
            }
            // advance ring counters
            k++;
            kb = (kb == 2) ? 0 : kb + 1;
            pb = (pb == 2) ? 0 : pb + 1;
        }

        // ---- epilogue (f16x2 tanh), overlaps next tile's in-flight loads ----
        const int Cg  = (tile & 127) * 2 + wc;
        const int gcb = gc0 + wc * 64;

        float p0[4] = {0.0f, 0.0f, 0.0f, 0.0f};
        float p1[4] = {0.0f, 0.0f, 0.0f, 0.0f};
        #pragma unroll
        for (int nt = 0; nt < 8; nt++) {
            int gcol = gcb + nt * 8 + 2 * tig;
            float2 bi = *(const float2*)(b_in + gcol);
            float2 gt = *(const float2*)(g_gate + gcol);
            #pragma unroll
            for (int mt = 0; mt < 4; mt++) {
                __half2 hv0 = __floats2half2_rn(d[mt][nt][0] + bi.x, d[mt][nt][1] + bi.y);
                __half2 hv1 = __floats2half2_rn(d[mt][nt][2] + bi.x, d[mt][nt][3] + bi.y);
                uint32_t h0 = *(uint32_t*)&hv0;
                uint32_t h1 = *(uint32_t*)&hv1;
                asm("tanh.approx.f16x2 %0, %0;" : "+r"(h0));
                asm("tanh.approx.f16x2 %0, %0;" : "+r"(h1));
                float2 t0 = __half22float2(*(__half2*)&h0);
                float2 t1 = __half22float2(*(__half2*)&h1);
                p0[mt] += t0.x * gt.x + t0.y * gt.y;
                p1[mt] += t1.x * gt.x + t1.y * gt.y;
            }
        }
        #pragma unroll
        for (int off = 1; off <= 2; off <<= 1) {
            #pragma unroll
            for (int mt = 0; mt < 4; mt++) {
                p0[mt] += __shfl_xor_sync(0xffffffffu, p0[mt], off);
                p1[mt] += __shfl_xor_sync(0xffffffffu, p1[mt], off);
            }
        }
        if (tig == 0) {
            float bo = __ldg(b_out + Cg);
            #pragma unroll
            for (int mt = 0; mt < 4; mt++) {
                int r0 = m0 + wr * 64 + mt * 16 + g;
                out[r0 * V + Cg]       = p0[mt] + bo;
                out[(r0 + 8) * V + Cg] = p1[mt] + bo;
            }
        }
    }
}

// ---------------------------------------------------------------------------
extern "C" void kernel_launch(void* const* d_in, const int* in_sizes, int n_in,
                              void* d_out, int out_size) {
    const float* data    = (const float*)d_in[0];
    const float* adj     = (const float*)d_in[1];
    const float* neurons = (const float*)d_in[2];
    const float* w_in    = (const float*)d_in[3];
    const float* b_in    = (const float*)d_in[4];
    const float* w_out   = (const float*)d_in[5];
    const float* b_out   = (const float*)d_in[6];
    // d_in[7] = perm: analytic, never read.

    float* outp = (float*)d_out;
    int adj_off = out_size - N_SAMP * V;   // V*V = 65536
    float* out_main = outp + (adj_off > 0 ? adj_off : 0);

    prep_kernel<<<2048, 256>>>((const float4*)data, adj, neurons, w_in, w_out,
                               (float4*)outp);

    cudaFuncSetAttribute(fused_mma_kernel,
                         cudaFuncAttributeMaxDynamicSharedMemorySize, SMEM_TOTAL);
    fused_mma_kernel<<<GRID_MAIN, 128, SMEM_TOTAL>>>(b_in, b_out, out_main);
}

// round 12
// speedup vs baseline: 1.0363x; 1.0363x over previous
#include <cuda_runtime.h>
#include <cuda_fp16.h>
#include <cstdint>

#define N_SAMP 4096
#define V 256
#define VM1 255
#define NH 64
#define NCOLS (V * NH)   // 16384

__device__ __half g_Ah[N_SAMP * V];   // data as fp16 [4096][256]
__device__ __half g_Bh[NCOLS * V];    // B^T: [gc][j]
__device__ float  g_gate[NCOLS];      // neurons[h,c]*w_out[c,h]

__device__ __forceinline__ uint32_t smem_u32(const void* p) {
    uint32_t a;
    asm("{ .reg .u64 t; cvta.to.shared.u64 t, %1; cvt.u32.u64 %0, t; }" : "=r"(a) : "l"(p));
    return a;
}
#define CP_ASYNC16(dst_u32, src_ptr) \
    asm volatile("cp.async.cg.shared.global [%0], [%1], 16;" :: "r"(dst_u32), "l"(src_ptr) : "memory")
#define CP_COMMIT() asm volatile("cp.async.commit_group;" ::: "memory")

// ---------------------------------------------------------------------------
// Merged prep (unchanged)
// ---------------------------------------------------------------------------
__global__ __launch_bounds__(256) void prep_kernel(
    const float4* __restrict__ data4,
    const float*  __restrict__ adj,
    const float*  __restrict__ neurons,
    const float*  __restrict__ w_in,
    const float*  __restrict__ w_out,
    float4* __restrict__ out_adj4)
{
    __shared__ float s[64][65];
    __shared__ float adjv[64];
    const int tid = threadIdx.x;

    if (blockIdx.x < 1024) {
        int idx = blockIdx.x * 256 + tid;
        if (idx < (N_SAMP * V) / 4) {
            float4 v = data4[idx];
            __half2* dst = (__half2*)(g_Ah + idx * 4);
            dst[0] = __floats2half2_rn(v.x, v.y);
            dst[1] = __floats2half2_rn(v.z, v.w);
        }
        if (idx < (V * V) / 4) out_adj4[idx] = ((const float4*)adj)[idx];
        if (idx < NCOLS / 4) {
            int gc = idx * 4;
            int c = gc >> 6, h = gc & 63;
            float4 g;
            g.x = neurons[(h + 0) * V + c] * w_out[gc + 0];
            g.y = neurons[(h + 1) * V + c] * w_out[gc + 1];
            g.z = neurons[(h + 2) * V + c] * w_out[gc + 2];
            g.w = neurons[(h + 3) * V + c] * w_out[gc + 3];
            *(float4*)(g_gate + gc) = g;
        }
    } else {
        const int bid = blockIdx.x - 1024;
        const int c   = bid >> 2;
        const int jb  = bid & 3;
        const int h   = tid & 63;
        const int kk4 = tid >> 6;

        if (tid < 64) {
            int j = jb * 64 + tid;
            adjv[tid] = (j == c) ? 0.0f : adj[j * V + c];
        }
        #pragma unroll
        for (int jj0 = 0; jj0 < 64; jj0 += 4) {
            int jj = jj0 + kk4;
            int j  = jb * 64 + jj;
            float w = 0.0f;
            if (j != c) {
                int k = j - (j > c ? 1 : 0);
                w = w_in[(c * VM1 + k) * NH + h];
            }
            s[jj][h] = w;
        }
        __syncthreads();
        #pragma unroll
        for (int h0 = 0; h0 < 64; h0 += 4) {
            int hh = h0 + (tid >> 6);
            int jj = tid & 63;
            float w = s[jj][hh] * adjv[jj];
            g_Bh[(c * 64 + hh) * V + jb * 64 + jj] = __float2half_rn(w);
        }
    }
}

// ---------------------------------------------------------------------------
// Fused GEMM (mma.sync m16n8k16 fp16->fp32) + f16x2-tanh/gate/h-reduce.
// CTA: 128x128, 4 warps as 2x2, warp tile 64x64. BK=64, 3-stage cp.async
// pipeline, ONE __syncthreads per stage. 128 threads, 2 CTAs/SM.
// ---------------------------------------------------------------------------
#define BK 64
#define A_STAGE_BYTES 16384
#define STAGE_BYTES 32768                 // A 16KB + B 16KB
#define NSTAGE 3
#define SMEM_TOTAL (NSTAGE * STAGE_BYTES) // 96KB

__device__ __forceinline__ void prefetch_stage(uint32_t sbuf, int m0, int gc0,
                                               int k0, int ldr, int ldq) {
    uint32_t sa = sbuf, sB = sbuf + A_STAGE_BYTES;
    #pragma unroll
    for (int i = 0; i < 8; i++) {
        int r = ldr + i * 16;
        uint32_t dsw = (uint32_t)(r * 128 + ((ldq ^ (r & 7)) << 4));
        CP_ASYNC16(sa + dsw, g_Ah + (m0 + r) * V + k0 + ldq * 8);
        CP_ASYNC16(sB + dsw, g_Bh + (gc0 + r) * V + k0 + ldq * 8);
    }
}

__global__ __launch_bounds__(128, 2)
void fused_mma_kernel(const float* __restrict__ b_in,
                      const float* __restrict__ b_out,
                      float* __restrict__ out) {
    extern __shared__ __align__(16) char smem[];
    const uint32_t sb = smem_u32(smem);

    const int tid  = threadIdx.x;
    const int wid  = tid >> 5;
    const int lane = tid & 31;
    const int wr   = wid & 1;
    const int wc   = wid >> 1;
    const int ldr  = tid >> 3;
    const int ldq  = tid & 7;
    const int g    = lane >> 2;
    const int tig  = lane & 3;

    const int m0  = blockIdx.y * 128;
    const int gc0 = blockIdx.x * 128;

    float d[4][8][4];
    #pragma unroll
    for (int mt = 0; mt < 4; mt++)
        #pragma unroll
        for (int nt = 0; nt < 8; nt++)
            #pragma unroll
            for (int v = 0; v < 4; v++) d[mt][nt][v] = 0.0f;

    // ---- preamble: prefetch stages 0 and 1 (two commit groups) ----
    prefetch_stage(sb,               m0, gc0, 0 * BK, ldr, ldq);
    CP_COMMIT();
    prefetch_stage(sb + STAGE_BYTES, m0, gc0, 1 * BK, ldr, ldq);
    CP_COMMIT();

    #pragma unroll
    for (int t = 0; t < 4; t++) {
        if (t < 3) asm volatile("cp.async.wait_group 1;" ::: "memory");
        else       asm volatile("cp.async.wait_group 0;" ::: "memory");
        __syncthreads();

        if (t + 2 <= 3) {
            prefetch_stage(sb + (uint32_t)(((t + 2) % NSTAGE) * STAGE_BYTES),
                           m0, gc0, (t + 2) * BK, ldr, ldq);
            CP_COMMIT();
        }

        const uint32_t sa = sb + (uint32_t)((t % NSTAGE) * STAGE_BYTES);
        const uint32_t sB = sa + A_STAGE_BYTES;

        #pragma unroll
        for (int ks = 0; ks < 4; ks++) {
            uint32_t a[4][4];
            #pragma unroll
            for (int mt = 0; mt < 4; mt++) {
                int r = wr * 64 + mt * 16 + (lane & 15);
                int q = ks * 2 + (lane >> 4);
                uint32_t addr = sa + r * 128 + ((q ^ (r & 7)) << 4);
                asm volatile("ldmatrix.sync.aligned.m8n8.x4.shared.b16 {%0,%1,%2,%3}, [%4];"
                    : "=r"(a[mt][0]), "=r"(a[mt][1]), "=r"(a[mt][2]), "=r"(a[mt][3])
                    : "r"(addr));
            }
            uint32_t bf[8][2];
            #pragma unroll
            for (int p = 0; p < 4; p++) {
                int r = wc * 64 + p * 16 + (lane & 7) + ((lane >> 4) << 3);
                int q = ks * 2 + ((lane >> 3) & 1);
                uint32_t addr = sB + r * 128 + ((q ^ (r & 7)) << 4);
                uint32_t r0, r1, r2, r3;
                asm volatile("ldmatrix.sync.aligned.m8n8.x4.shared.b16 {%0,%1,%2,%3}, [%4];"
                    : "=r"(r0), "=r"(r1), "=r"(r2), "=r"(r3) : "r"(addr));
                bf[p * 2][0] = r0; bf[p * 2][1] = r1;
                bf[p * 2 + 1][0] = r2; bf[p * 2 + 1][1] = r3;
            }
            #pragma unroll
            for (int mt = 0; mt < 4; mt++)
                #pragma unroll
                for (int nt = 0; nt < 8; nt++) {
                    asm volatile(
                        "mma.sync.aligned.m16n8k16.row.col.f32.f16.f16.f32 "
                        "{%0,%1,%2,%3}, {%4,%5,%6,%7}, {%8,%9}, {%0,%1,%2,%3};"
                        : "+f"(d[mt][nt][0]), "+f"(d[mt][nt][1]),
                          "+f"(d[mt][nt][2]), "+f"(d[mt][nt][3])
                        : "r"(a[mt][0]), "r"(a[mt][1]), "r"(a[mt][2]), "r"(a[mt][3]),
                          "r"(bf[nt][0]), "r"(bf[nt][1]));
                }
        }
    }

    // ---- epilogue: f16x2 tanh (validated rel_err ~5e-4), gate, h-reduce ----
    const int Cg  = blockIdx.x * 2 + wc;
    const int gcb = gc0 + wc * 64;

    float p0[4] = {0.0f, 0.0f, 0.0f, 0.0f};
    float p1[4] = {0.0f, 0.0f, 0.0f, 0.0f};
    #pragma unroll
    for (int nt = 0; nt < 8; nt++) {
        int gcol = gcb + nt * 8 + 2 * tig;
        float2 bi = *(const float2*)(b_in + gcol);
        float2 gt = *(const float2*)(g_gate + gcol);
        #pragma unroll
        for (int mt = 0; mt < 4; mt++) {
            __half2 hv0 = __floats2half2_rn(d[mt][nt][0] + bi.x, d[mt][nt][1] + bi.y);
            __half2 hv1 = __floats2half2_rn(d[mt][nt][2] + bi.x, d[mt][nt][3] + bi.y);
            uint32_t h0 = *(uint32_t*)&hv0;
            uint32_t h1 = *(uint32_t*)&hv1;
            asm("tanh.approx.f16x2 %0, %0;" : "+r"(h0));
            asm("tanh.approx.f16x2 %0, %0;" : "+r"(h1));
            float2 t0 = __half22float2(*(__half2*)&h0);
            float2 t1 = __half22float2(*(__half2*)&h1);
            p0[mt] += t0.x * gt.x + t0.y * gt.y;
            p1[mt] += t1.x * gt.x + t1.y * gt.y;
        }
    }
    #pragma unroll
    for (int off = 1; off <= 2; off <<= 1) {
        #pragma unroll
        for (int mt = 0; mt < 4; mt++) {
            p0[mt] += __shfl_xor_sync(0xffffffffu, p0[mt], off);
            p1[mt] += __shfl_xor_sync(0xffffffffu, p1[mt], off);
        }
    }
    if (tig == 0) {
        float bo = __ldg(b_out + Cg);
        #pragma unroll
        for (int mt = 0; mt < 4; mt++) {
            int r0 = m0 + wr * 64 + mt * 16 + g;
            out[r0 * V + Cg]       = p0[mt] + bo;
            out[(r0 + 8) * V + Cg] = p1[mt] + bo;
        }
    }
}

// ---------------------------------------------------------------------------
extern "C" void kernel_launch(void* const* d_in, const int* in_sizes, int n_in,
                              void* d_out, int out_size) {
    const float* data    = (const float*)d_in[0];
    const float* adj     = (const float*)d_in[1];
    const float* neurons = (const float*)d_in[2];
    const float* w_in    = (const float*)d_in[3];
    const float* b_in    = (const float*)d_in[4];
    const float* w_out   = (const float*)d_in[5];
    const float* b_out   = (const float*)d_in[6];
    // d_in[7] = perm: analytic, never read.

    float* outp = (float*)d_out;
    int adj_off = out_size - N_SAMP * V;   // V*V = 65536
    float* out_main = outp + (adj_off > 0 ? adj_off : 0);

    prep_kernel<<<2048, 256>>>((const float4*)data, adj, neurons, w_in, w_out,
                               (float4*)outp);

    cudaFuncSetAttribute(fused_mma_kernel,
                         cudaFuncAttributeMaxDynamicSharedMemorySize, SMEM_TOTAL);
    dim3 grid(NCOLS / 128, N_SAMP / 128);
    fused_mma_kernel<<<grid, 128, SMEM_TOTAL>>>(b_in, b_out, out_main);
}

// round 13
// speedup vs baseline: 1.1534x; 1.1130x over previous
#include <cuda_runtime.h>
#include <cuda_fp16.h>
#include <cstdint>

#define N_SAMP 4096
#define V 256
#define VM1 255
#define NH 64
#define NCOLS (V * NH)   // 16384

__device__ __half g_Ah[N_SAMP * V];   // data as fp16 [4096][256]
__device__ __half g_Bh[NCOLS * V];    // B^T: [gc][j]
__device__ float  g_gate[NCOLS];      // neurons[h,c]*w_out[c,h]
__device__ __half g_binh[NCOLS];      // b_in as fp16

__device__ __forceinline__ uint32_t smem_u32(const void* p) {
    uint32_t a;
    asm("{ .reg .u64 t; cvta.to.shared.u64 t, %1; cvt.u32.u64 %0, t; }" : "=r"(a) : "l"(p));
    return a;
}
#define CP_ASYNC16(dst_u32, src_ptr) \
    asm volatile("cp.async.cg.shared.global [%0], [%1], 16;" :: "r"(dst_u32), "l"(src_ptr) : "memory")
#define CP_COMMIT() asm volatile("cp.async.commit_group;" ::: "memory")

// ---------------------------------------------------------------------------
// Merged prep (adds b_in -> fp16)
// ---------------------------------------------------------------------------
__global__ __launch_bounds__(256) void prep_kernel(
    const float4* __restrict__ data4,
    const float*  __restrict__ adj,
    const float*  __restrict__ neurons,
    const float*  __restrict__ w_in,
    const float*  __restrict__ w_out,
    const float*  __restrict__ b_in,
    float4* __restrict__ out_adj4)
{
    __shared__ float s[64][65];
    __shared__ float adjv[64];
    const int tid = threadIdx.x;

    if (blockIdx.x < 1024) {
        int idx = blockIdx.x * 256 + tid;
        if (idx < (N_SAMP * V) / 4) {
            float4 v = data4[idx];
            __half2* dst = (__half2*)(g_Ah + idx * 4);
            dst[0] = __floats2half2_rn(v.x, v.y);
            dst[1] = __floats2half2_rn(v.z, v.w);
        }
        if (idx < (V * V) / 4) out_adj4[idx] = ((const float4*)adj)[idx];
        if (idx < NCOLS / 4) {
            int gc = idx * 4;
            int c = gc >> 6, h = gc & 63;
            float4 g;
            g.x = neurons[(h + 0) * V + c] * w_out[gc + 0];
            g.y = neurons[(h + 1) * V + c] * w_out[gc + 1];
            g.z = neurons[(h + 2) * V + c] * w_out[gc + 2];
            g.w = neurons[(h + 3) * V + c] * w_out[gc + 3];
            *(float4*)(g_gate + gc) = g;
            __half2* bh = (__half2*)(g_binh + gc);
            bh[0] = __floats2half2_rn(b_in[gc + 0], b_in[gc + 1]);
            bh[1] = __floats2half2_rn(b_in[gc + 2], b_in[gc + 3]);
        }
    } else {
        const int bid = blockIdx.x - 1024;
        const int c   = bid >> 2;
        const int jb  = bid & 3;
        const int h   = tid & 63;
        const int kk4 = tid >> 6;

        if (tid < 64) {
            int j = jb * 64 + tid;
            adjv[tid] = (j == c) ? 0.0f : adj[j * V + c];
        }
        #pragma unroll
        for (int jj0 = 0; jj0 < 64; jj0 += 4) {
            int jj = jj0 + kk4;
            int j  = jb * 64 + jj;
            float w = 0.0f;
            if (j != c) {
                int k = j - (j > c ? 1 : 0);
                w = w_in[(c * VM1 + k) * NH + h];
            }
            s[jj][h] = w;
        }
        __syncthreads();
        #pragma unroll
        for (int h0 = 0; h0 < 64; h0 += 4) {
            int hh = h0 + (tid >> 6);
            int jj = tid & 63;
            float w = s[jj][hh] * adjv[jj];
            g_Bh[(c * 64 + hh) * V + jb * 64 + jj] = __float2half_rn(w);
        }
    }
}

// ---------------------------------------------------------------------------
// Fused GEMM (mma.sync m16n8k16, fp16 accum in two compile-time K-half banks)
// + f16x2 tanh/gate/h-reduce. CTA 128x128, 4 warps 2x2, warp tile 64x64.
// BK=64, 2-stage double buffer; __launch_bounds__(128,3) -> 3 CTAs/SM.
// ---------------------------------------------------------------------------
#define BK 64
#define A_STAGE_BYTES 16384
#define STAGE_BYTES 32768                 // A 16KB + B 16KB
#define SMEM_TOTAL (2 * STAGE_BYTES)      // 64KB

__device__ __forceinline__ void prefetch_stage(uint32_t sbuf, int m0, int gc0,
                                               int k0, int ldr, int ldq) {
    uint32_t sa = sbuf, sB = sbuf + A_STAGE_BYTES;
    #pragma unroll
    for (int i = 0; i < 8; i++) {
        int r = ldr + i * 16;
        uint32_t dsw = (uint32_t)(r * 128 + ((ldq ^ (r & 7)) << 4));
        CP_ASYNC16(sa + dsw, g_Ah + (m0 + r) * V + k0 + ldq * 8);
        CP_ASYNC16(sB + dsw, g_Bh + (gc0 + r) * V + k0 + ldq * 8);
    }
}

#define MMA_F16ACC(acc, aa, bb) \
    asm volatile("mma.sync.aligned.m16n8k16.row.col.f16.f16.f16.f16 " \
        "{%0,%1}, {%2,%3,%4,%5}, {%6,%7}, {%0,%1};" \
        : "+r"((acc)[0]), "+r"((acc)[1]) \
        : "r"((aa)[0]), "r"((aa)[1]), "r"((aa)[2]), "r"((aa)[3]), \
          "r"((bb)[0]), "r"((bb)[1]))

__global__ __launch_bounds__(128, 3)
void fused_mma_kernel(const float* __restrict__ b_out,
                      float* __restrict__ out) {
    extern __shared__ __align__(16) char smem[];
    const uint32_t sb = smem_u32(smem);

    const int tid  = threadIdx.x;
    const int wid  = tid >> 5;
    const int lane = tid & 31;
    const int wr   = wid & 1;
    const int wc   = wid >> 1;
    const int ldr  = tid >> 3;
    const int ldq  = tid & 7;
    const int g    = lane >> 2;
    const int tig  = lane & 3;

    const int m0  = blockIdx.y * 128;
    const int gc0 = blockIdx.x * 128;

    // two fp16 accumulator banks: K[0,128) and K[128,256)
    uint32_t dlo[4][8][2], dhi[4][8][2];
    #pragma unroll
    for (int mt = 0; mt < 4; mt++)
        #pragma unroll
        for (int nt = 0; nt < 8; nt++) {
            dlo[mt][nt][0] = 0u; dlo[mt][nt][1] = 0u;
            dhi[mt][nt][0] = 0u; dhi[mt][nt][1] = 0u;
        }

    prefetch_stage(sb, m0, gc0, 0, ldr, ldq);
    CP_COMMIT();

    #pragma unroll
    for (int t = 0; t < 4; t++) {
        if (t < 3) {
            prefetch_stage(sb + (uint32_t)(((t + 1) & 1) * STAGE_BYTES),
                           m0, gc0, (t + 1) * BK, ldr, ldq);
            CP_COMMIT();
            asm volatile("cp.async.wait_group 1;" ::: "memory");
        } else {
            asm volatile("cp.async.wait_group 0;" ::: "memory");
        }
        __syncthreads();

        const uint32_t sa = sb + (uint32_t)((t & 1) * STAGE_BYTES);
        const uint32_t sB = sa + A_STAGE_BYTES;

        #pragma unroll
        for (int ks = 0; ks < 4; ks++) {
            uint32_t a[4][4];
            #pragma unroll
            for (int mt = 0; mt < 4; mt++) {
                int r = wr * 64 + mt * 16 + (lane & 15);
                int q = ks * 2 + (lane >> 4);
                uint32_t addr = sa + r * 128 + ((q ^ (r & 7)) << 4);
                asm volatile("ldmatrix.sync.aligned.m8n8.x4.shared.b16 {%0,%1,%2,%3}, [%4];"
                    : "=r"(a[mt][0]), "=r"(a[mt][1]), "=r"(a[mt][2]), "=r"(a[mt][3])
                    : "r"(addr));
            }
            uint32_t bf[8][2];
            #pragma unroll
            for (int p = 0; p < 4; p++) {
                int r = wc * 64 + p * 16 + (lane & 7) + ((lane >> 4) << 3);
                int q = ks * 2 + ((lane >> 3) & 1);
                uint32_t addr = sB + r * 128 + ((q ^ (r & 7)) << 4);
                uint32_t r0, r1, r2, r3;
                asm volatile("ldmatrix.sync.aligned.m8n8.x4.shared.b16 {%0,%1,%2,%3}, [%4];"
                    : "=r"(r0), "=r"(r1), "=r"(r2), "=r"(r3) : "r"(addr));
                bf[p * 2][0] = r0; bf[p * 2][1] = r1;
                bf[p * 2 + 1][0] = r2; bf[p * 2 + 1][1] = r3;
            }
            // compile-time bank select (t loop fully unrolled)
            if (t < 2) {
                #pragma unroll
                for (int mt = 0; mt < 4; mt++)
                    #pragma unroll
                    for (int nt = 0; nt < 8; nt++)
                        MMA_F16ACC(dlo[mt][nt], a[mt], bf[nt]);
            } else {
                #pragma unroll
                for (int mt = 0; mt < 4; mt++)
                    #pragma unroll
                    for (int nt = 0; nt < 8; nt++)
                        MMA_F16ACC(dhi[mt][nt], a[mt], bf[nt]);
            }
        }
        __syncthreads();
    }

    // ---- epilogue: pre = lo + hi + bias (fp16), tanh.f16x2, f32 gate/reduce
    const int Cg  = blockIdx.x * 2 + wc;
    const int gcb = gc0 + wc * 64;

    float p0[4] = {0.0f, 0.0f, 0.0f, 0.0f};
    float p1[4] = {0.0f, 0.0f, 0.0f, 0.0f};
    #pragma unroll
    for (int nt = 0; nt < 8; nt++) {
        int gcol = gcb + nt * 8 + 2 * tig;               // even
        float2  gt  = *(const float2*)(g_gate + gcol);
        __half2 bih = *(const __half2*)(g_binh + gcol);
        #pragma unroll
        for (int mt = 0; mt < 4; mt++) {
            __half2 s0 = __hadd2(__hadd2(*(__half2*)&dlo[mt][nt][0],
                                         *(__half2*)&dhi[mt][nt][0]), bih);
            __half2 s1 = __hadd2(__hadd2(*(__half2*)&dlo[mt][nt][1],
                                         *(__half2*)&dhi[mt][nt][1]), bih);
            uint32_t u0 = *(uint32_t*)&s0;
            uint32_t u1 = *(uint32_t*)&s1;
            asm("tanh.approx.f16x2 %0, %0;" : "+r"(u0));
            asm("tanh.approx.f16x2 %0, %0;" : "+r"(u1));
            float2 t0 = __half22float2(*(__half2*)&u0);
            float2 t1 = __half22float2(*(__half2*)&u1);
            p0[mt] += t0.x * gt.x + t0.y * gt.y;
            p1[mt] += t1.x * gt.x + t1.y * gt.y;
        }
    }
    #pragma unroll
    for (int off = 1; off <= 2; off <<= 1) {
        #pragma unroll
        for (int mt = 0; mt < 4; mt++) {
            p0[mt] += __shfl_xor_sync(0xffffffffu, p0[mt], off);
            p1[mt] += __shfl_xor_sync(0xffffffffu, p1[mt], off);
        }
    }
    if (tig == 0) {
        float bo = __ldg(b_out + Cg);
        #pragma unroll
        for (int mt = 0; mt < 4; mt++) {
            int r0 = m0 + wr * 64 + mt * 16 + g;
            out[r0 * V + Cg]       = p0[mt] + bo;
            out[(r0 + 8) * V + Cg] = p1[mt] + bo;
        }
    }
}

// ---------------------------------------------------------------------------
extern "C" void kernel_launch(void* const* d_in, const int* in_sizes, int n_in,
                              void* d_out, int out_size) {
    const float* data    = (const float*)d_in[0];
    const float* adj     = (const float*)d_in[1];
    const float* neurons = (const float*)d_in[2];
    const float* w_in    = (const float*)d_in[3];
    const float* b_in    = (const float*)d_in[4];
    const float* w_out   = (const float*)d_in[5];
    const float* b_out   = (const float*)d_in[6];
    // d_in[7] = perm: analytic, never read.

    float* outp = (float*)d_out;
    int adj_off = out_size - N_SAMP * V;   // V*V = 65536
    float* out_main = outp + (adj_off > 0 ? adj_off : 0);

    prep_kernel<<<2048, 256>>>((const float4*)data, adj, neurons, w_in, w_out,
                               b_in, (float4*)outp);

    cudaFuncSetAttribute(fused_mma_kernel,
                         cudaFuncAttributeMaxDynamicSharedMemorySize, SMEM_TOTAL);
    dim3 grid(NCOLS / 128, N_SAMP / 128);
    fused_mma_kernel<<<grid, 128, SMEM_TOTAL>>>(b_out, out_main);
}

// round 14
// speedup vs baseline: 1.1799x; 1.0229x over previous
#include <cuda_runtime.h>
#include <cuda_fp16.h>
#include <cstdint>

#define N_SAMP 4096
#define V 256
#define VM1 255
#define NH 64
#define NCOLS (V * NH)   // 16384

__device__ __half g_Ah[N_SAMP * V];   // data as fp16 [4096][256]
__device__ __half g_Bh[NCOLS * V];    // B^T: [gc][j]
__device__ float  g_gate[NCOLS];      // neurons[h,c]*w_out[c,h]
__device__ __half g_binh[NCOLS];      // b_in as fp16

__device__ __forceinline__ uint32_t smem_u32(const void* p) {
    uint32_t a;
    asm("{ .reg .u64 t; cvta.to.shared.u64 t, %1; cvt.u32.u64 %0, t; }" : "=r"(a) : "l"(p));
    return a;
}
#define CP_ASYNC16(dst_u32, src_ptr) \
    asm volatile("cp.async.cg.shared.global [%0], [%1], 16;" :: "r"(dst_u32), "l"(src_ptr) : "memory")
#define CP_COMMIT() asm volatile("cp.async.commit_group;" ::: "memory")

// ---------------------------------------------------------------------------
// Merged prep (unchanged from R13)
// ---------------------------------------------------------------------------
__global__ __launch_bounds__(256) void prep_kernel(
    const float4* __restrict__ data4,
    const float*  __restrict__ adj,
    const float*  __restrict__ neurons,
    const float*  __restrict__ w_in,
    const float*  __restrict__ w_out,
    const float*  __restrict__ b_in,
    float4* __restrict__ out_adj4)
{
    __shared__ float s[64][65];
    __shared__ float adjv[64];
    const int tid = threadIdx.x;

    if (blockIdx.x < 1024) {
        int idx = blockIdx.x * 256 + tid;
        if (idx < (N_SAMP * V) / 4) {
            float4 v = data4[idx];
            __half2* dst = (__half2*)(g_Ah + idx * 4);
            dst[0] = __floats2half2_rn(v.x, v.y);
            dst[1] = __floats2half2_rn(v.z, v.w);
        }
        if (idx < (V * V) / 4) out_adj4[idx] = ((const float4*)adj)[idx];
        if (idx < NCOLS / 4) {
            int gc = idx * 4;
            int c = gc >> 6, h = gc & 63;
            float4 g;
            g.x = neurons[(h + 0) * V + c] * w_out[gc + 0];
            g.y = neurons[(h + 1) * V + c] * w_out[gc + 1];
            g.z = neurons[(h + 2) * V + c] * w_out[gc + 2];
            g.w = neurons[(h + 3) * V + c] * w_out[gc + 3];
            *(float4*)(g_gate + gc) = g;
            __half2* bh = (__half2*)(g_binh + gc);
            bh[0] = __floats2half2_rn(b_in[gc + 0], b_in[gc + 1]);
            bh[1] = __floats2half2_rn(b_in[gc + 2], b_in[gc + 3]);
        }
    } else {
        const int bid = blockIdx.x - 1024;
        const int c   = bid >> 2;
        const int jb  = bid & 3;
        const int h   = tid & 63;
        const int kk4 = tid >> 6;

        if (tid < 64) {
            int j = jb * 64 + tid;
            adjv[tid] = (j == c) ? 0.0f : adj[j * V + c];
        }
        #pragma unroll
        for (int jj0 = 0; jj0 < 64; jj0 += 4) {
            int jj = jj0 + kk4;
            int j  = jb * 64 + jj;
            float w = 0.0f;
            if (j != c) {
                int k = j - (j > c ? 1 : 0);
                w = w_in[(c * VM1 + k) * NH + h];
            }
            s[jj][h] = w;
        }
        __syncthreads();
        #pragma unroll
        for (int h0 = 0; h0 < 64; h0 += 4) {
            int hh = h0 + (tid >> 6);
            int jj = tid & 63;
            float w = s[jj][hh] * adjv[jj];
            g_Bh[(c * 64 + hh) * V + jb * 64 + jj] = __float2half_rn(w);
        }
    }
}

// ---------------------------------------------------------------------------
// Fused GEMM (mma.sync m16n8k16, fp16 accum in two compile-time K-half banks)
// + f16x2 tanh/gate/h-reduce. CTA 128x128, 4 warps 2x2, warp tile 64x64.
// BK=64, 2-stage double buffer, ONE __syncthreads per stage (wait-first
// reorder makes the single barrier cover both RAW and WAR).
// __launch_bounds__(128,3) -> 3 CTAs/SM.
// ---------------------------------------------------------------------------
#define BK 64
#define A_STAGE_BYTES 16384
#define STAGE_BYTES 32768                 // A 16KB + B 16KB
#define SMEM_TOTAL (2 * STAGE_BYTES)      // 64KB

__device__ __forceinline__ void prefetch_stage(uint32_t sbuf, int m0, int gc0,
                                               int k0, int ldr, int ldq) {
    uint32_t sa = sbuf, sB = sbuf + A_STAGE_BYTES;
    #pragma unroll
    for (int i = 0; i < 8; i++) {
        int r = ldr + i * 16;
        uint32_t dsw = (uint32_t)(r * 128 + ((ldq ^ (r & 7)) << 4));
        CP_ASYNC16(sa + dsw, g_Ah + (m0 + r) * V + k0 + ldq * 8);
        CP_ASYNC16(sB + dsw, g_Bh + (gc0 + r) * V + k0 + ldq * 8);
    }
}

#define MMA_F16ACC(acc, aa, bb) \
    asm volatile("mma.sync.aligned.m16n8k16.row.col.f16.f16.f16.f16 " \
        "{%0,%1}, {%2,%3,%4,%5}, {%6,%7}, {%0,%1};" \
        : "+r"((acc)[0]), "+r"((acc)[1]) \
        : "r"((aa)[0]), "r"((aa)[1]), "r"((aa)[2]), "r"((aa)[3]), \
          "r"((bb)[0]), "r"((bb)[1]))

__global__ __launch_bounds__(128, 3)
void fused_mma_kernel(const float* __restrict__ b_out,
                      float* __restrict__ out) {
    extern __shared__ __align__(16) char smem[];
    const uint32_t sb = smem_u32(smem);

    const int tid  = threadIdx.x;
    const int wid  = tid >> 5;
    const int lane = tid & 31;
    const int wr   = wid & 1;
    const int wc   = wid >> 1;
    const int ldr  = tid >> 3;
    const int ldq  = tid & 7;
    const int g    = lane >> 2;
    const int tig  = lane & 3;

    const int m0  = blockIdx.y * 128;
    const int gc0 = blockIdx.x * 128;

    // two fp16 accumulator banks: K[0,128) and K[128,256)
    uint32_t dlo[4][8][2], dhi[4][8][2];
    #pragma unroll
    for (int mt = 0; mt < 4; mt++)
        #pragma unroll
        for (int nt = 0; nt < 8; nt++) {
            dlo[mt][nt][0] = 0u; dlo[mt][nt][1] = 0u;
            dhi[mt][nt][0] = 0u; dhi[mt][nt][1] = 0u;
        }

    prefetch_stage(sb, m0, gc0, 0, ldr, ldq);
    CP_COMMIT();

    #pragma unroll
    for (int t = 0; t < 4; t++) {
        // pending groups == {t} here; drain it, then one barrier gives
        // (a) stage-t visibility across threads, (b) WAR safety for buf (t+1)&1
        asm volatile("cp.async.wait_group 0;" ::: "memory");
        __syncthreads();

        if (t < 3) {
            prefetch_stage(sb + (uint32_t)(((t + 1) & 1) * STAGE_BYTES),
                           m0, gc0, (t + 1) * BK, ldr, ldq);
            CP_COMMIT();
        }

        const uint32_t sa = sb + (uint32_t)((t & 1) * STAGE_BYTES);
        const uint32_t sB = sa + A_STAGE_BYTES;

        #pragma unroll
        for (int ks = 0; ks < 4; ks++) {
            uint32_t a[4][4];
            #pragma unroll
            for (int mt = 0; mt < 4; mt++) {
                int r = wr * 64 + mt * 16 + (lane & 15);
                int q = ks * 2 + (lane >> 4);
                uint32_t addr = sa + r * 128 + ((q ^ (r & 7)) << 4);
                asm volatile("ldmatrix.sync.aligned.m8n8.x4.shared.b16 {%0,%1,%2,%3}, [%4];"
                    : "=r"(a[mt][0]), "=r"(a[mt][1]), "=r"(a[mt][2]), "=r"(a[mt][3])
                    : "r"(addr));
            }
            uint32_t bf[8][2];
            #pragma unroll
            for (int p = 0; p < 4; p++) {
                int r = wc * 64 + p * 16 + (lane & 7) + ((lane >> 4) << 3);
                int q = ks * 2 + ((lane >> 3) & 1);
                uint32_t addr = sB + r * 128 + ((q ^ (r & 7)) << 4);
                uint32_t r0, r1, r2, r3;
                asm volatile("ldmatrix.sync.aligned.m8n8.x4.shared.b16 {%0,%1,%2,%3}, [%4];"
                    : "=r"(r0), "=r"(r1), "=r"(r2), "=r"(r3) : "r"(addr));
                bf[p * 2][0] = r0; bf[p * 2][1] = r1;
                bf[p * 2 + 1][0] = r2; bf[p * 2 + 1][1] = r3;
            }
            if (t < 2) {
                #pragma unroll
                for (int mt = 0; mt < 4; mt++)
                    #pragma unroll
                    for (int nt = 0; nt < 8; nt++)
                        MMA_F16ACC(dlo[mt][nt], a[mt], bf[nt]);
            } else {
                #pragma unroll
                for (int mt = 0; mt < 4; mt++)
                    #pragma unroll
                    for (int nt = 0; nt < 8; nt++)
                        MMA_F16ACC(dhi[mt][nt], a[mt], bf[nt]);
            }
        }
    }

    // ---- epilogue: pre = lo + hi + bias (fp16), tanh.f16x2, f32 gate/reduce
    const int Cg  = blockIdx.x * 2 + wc;
    const int gcb = gc0 + wc * 64;

    float p0[4] = {0.0f, 0.0f, 0.0f, 0.0f};
    float p1[4] = {0.0f, 0.0f, 0.0f, 0.0f};
    #pragma unroll
    for (int nt = 0; nt < 8; nt++) {
        int gcol = gcb + nt * 8 + 2 * tig;
        float2  gt  = *(const float2*)(g_gate + gcol);
        __half2 bih = *(const __half2*)(g_binh + gcol);
        #pragma unroll
        for (int mt = 0; mt < 4; mt++) {
            __half2 s0 = __hadd2(__hadd2(*(__half2*)&dlo[mt][nt][0],
                                         *(__half2*)&dhi[mt][nt][0]), bih);
            __half2 s1 = __hadd2(__hadd2(*(__half2*)&dlo[mt][nt][1],
                                         *(__half2*)&dhi[mt][nt][1]), bih);
            uint32_t u0 = *(uint32_t*)&s0;
            uint32_t u1 = *(uint32_t*)&s1;
            asm("tanh.approx.f16x2 %0, %0;" : "+r"(u0));
            asm("tanh.approx.f16x2 %0, %0;" : "+r"(u1));
            float2 t0 = __half22float2(*(__half2*)&u0);
            float2 t1 = __half22float2(*(__half2*)&u1);
            p0[mt] += t0.x * gt.x + t0.y * gt.y;
            p1[mt] += t1.x * gt.x + t1.y * gt.y;
        }
    }
    #pragma unroll
    for (int off = 1; off <= 2; off <<= 1) {
        #pragma unroll
        for (int mt = 0; mt < 4; mt++) {
            p0[mt] += __shfl_xor_sync(0xffffffffu, p0[mt], off);
            p1[mt] += __shfl_xor_sync(0xffffffffu, p1[mt], off);
        }
    }
    if (tig == 0) {
        float bo = __ldg(b_out + Cg);
        #pragma unroll
        for (int mt = 0; mt < 4; mt++) {
            int r0 = m0 + wr * 64 + mt * 16 + g;
            out[r0 * V + Cg]       = p0[mt] + bo;
            out[(r0 + 8) * V + Cg] = p1[mt] + bo;
        }
    }
}

// ---------------------------------------------------------------------------
extern "C" void kernel_launch(void* const* d_in, const int* in_sizes, int n_in,
                              void* d_out, int out_size) {
    const float* data    = (const float*)d_in[0];
    const float* adj     = (const float*)d_in[1];
    const float* neurons = (const float*)d_in[2];
    const float* w_in    = (const float*)d_in[3];
    const float* b_in    = (const float*)d_in[4];
    const float* w_out   = (const float*)d_in[5];
    const float* b_out   = (const float*)d_in[6];
    // d_in[7] = perm: analytic, never read.

    float* outp = (float*)d_out;
    int adj_off = out_size - N_SAMP * V;   // V*V = 65536
    float* out_main = outp + (adj_off > 0 ? adj_off : 0);

    prep_kernel<<<2048, 256>>>((const float4*)data, adj, neurons, w_in, w_out,
                               b_in, (float4*)outp);

    cudaFuncSetAttribute(fused_mma_kernel,
                         cudaFuncAttributeMaxDynamicSharedMemorySize, SMEM_TOTAL);
    dim3 grid(NCOLS / 128, N_SAMP / 128);
    fused_mma_kernel<<<grid, 128, SMEM_TOTAL>>>(b_out, out_main);
}